// round 8
// baseline (speedup 1.0000x reference)
#include <cuda_runtime.h>
#include <cuda_bf16.h>
#include <cstdint>

#define IN_F   512
#define OUT_F  512
#define NBAT   8192
#define NFEAT  12                      // 1 raw x + 11 spline bases
#define KB     (IN_F * NFEAT)          // 6144  (K of one block: hi or lo)
#define ROWB   (KB * 2)                // 12288 B global row stride per block
#define NCHB   (KB / 64)               // 96 chunks per block
#define NU     (2 * NCHB)              // 192 pipeline iterations
#define M_TILE 128
#define N_TILE 256
#define A_BYTES 16384                  // 128 rows x 128 B
#define B_BYTES 32768                  // 256 rows x 128 B
#define STAGE_BYTES (A_BYTES + 2 * B_BYTES)       // 81920
#define SMEM_TOTAL  (2 * STAGE_BYTES)             // 163840

// ---------------- scratch (device globals: allocation-free) ----------------
__device__ __nv_bfloat16 g_Ah[(size_t)NBAT * KB];     // 100.7 MB
__device__ __nv_bfloat16 g_Al[(size_t)NBAT * KB];     // 100.7 MB
__device__ __nv_bfloat16 g_Bh[(size_t)OUT_F * KB];    // 6.3 MB
__device__ __nv_bfloat16 g_Bl[(size_t)OUT_F * KB];    // 6.3 MB

// ---------------- PTX helpers (base-sm_80+ only) ---------------------------
__device__ __forceinline__ uint32_t smem_u32(const void* p) {
    uint32_t a;
    asm("{ .reg .u64 t; cvta.to.shared.u64 t, %1; cvt.u32.u64 %0, t; }" : "=r"(a) : "l"(p));
    return a;
}
__device__ __forceinline__ void cp16(uint32_t dst, const void* src) {
    asm volatile("cp.async.cg.shared.global [%0], [%1], 16;" :: "r"(dst), "l"(src));
}
#define CP_COMMIT() asm volatile("cp.async.commit_group;" ::: "memory")
#define CP_WAIT_1() asm volatile("cp.async.wait_group 1;" ::: "memory")
#define CP_WAIT_0() asm volatile("cp.async.wait_group 0;" ::: "memory")

__device__ __forceinline__ void ldsm4(uint32_t& r0, uint32_t& r1, uint32_t& r2,
                                      uint32_t& r3, uint32_t addr) {
    asm volatile("ldmatrix.sync.aligned.m8n8.x4.shared.b16 {%0,%1,%2,%3}, [%4];"
                 : "=r"(r0), "=r"(r1), "=r"(r2), "=r"(r3) : "r"(addr));
}
__device__ __forceinline__ void mma16816(float& d0, float& d1, float& d2, float& d3,
                                         uint32_t a0, uint32_t a1, uint32_t a2, uint32_t a3,
                                         uint32_t b0, uint32_t b1) {
    asm volatile(
        "mma.sync.aligned.m16n8k16.row.col.f32.bf16.bf16.f32 "
        "{%0,%1,%2,%3}, {%4,%5,%6,%7}, {%8,%9}, {%0,%1,%2,%3};"
        : "+f"(d0), "+f"(d1), "+f"(d2), "+f"(d3)
        : "r"(a0), "r"(a1), "r"(a2), "r"(a3), "r"(b0), "r"(b1));
}
// 128-byte smem rows, XOR-(r&7) swizzle; k16 step s = XOR (s<<5) on the address.
__device__ __forceinline__ uint32_t swz(int r, int c) {
    return (uint32_t)(r * 128 + ((c ^ (r & 7)) << 4));
}

// ---------------- basis (identical math to all passing kernels) ------------
__device__ __forceinline__ void aug_features(float xr, float* bb) {
    float xc = fminf(fmaxf(xr, -2.0f), 2.0f);
    float g[15];
#pragma unroll
    for (int m = 0; m < 15; ++m) g[m] = fmaf((float)m, 2.0f / 14.0f, -1.0f);
    float b[14];
#pragma unroll
    for (int m = 0; m < 14; ++m) b[m] = (xc >= g[m] && xc < g[m + 1]) ? 1.0f : 0.0f;
#pragma unroll
    for (int k = 1; k <= 3; ++k) {
        float inv = 7.0f / (float)k;
#pragma unroll
        for (int m = 0; m < 14 - k; ++m)
            b[m] = (xc - g[m]) * inv * b[m] + (g[m + k + 1] - xc) * inv * b[m + 1];
    }
    bb[0] = xr;
#pragma unroll
    for (int j = 0; j < 11; ++j) bb[1 + j] = b[j];
}
__device__ __forceinline__ void pack3(const unsigned short* s, unsigned long long* w) {
#pragma unroll
    for (int j = 0; j < 3; ++j)
        w[j] = (unsigned long long)s[4 * j] |
               ((unsigned long long)s[4 * j + 1] << 16) |
               ((unsigned long long)s[4 * j + 2] << 32) |
               ((unsigned long long)s[4 * j + 3] << 48);
}

// ---------------- prep_B: weights -> hi/lo blocks --------------------------
__global__ __launch_bounds__(256) void prep_B(const float* __restrict__ bw,
                                              const float* __restrict__ sw) {
    int idx = blockIdx.x * 256 + threadIdx.x;        // (o, i)
    int o = idx >> 9, i = idx & 511;
    float v[NFEAT];
    v[0] = bw[(size_t)o * IN_F + i];
#pragma unroll
    for (int j = 0; j < 11; ++j) v[1 + j] = sw[((size_t)o * IN_F + i) * 11 + j];
    unsigned short sh[NFEAT], sl[NFEAT];
#pragma unroll
    for (int c = 0; c < NFEAT; ++c) {
        __nv_bfloat16 h = __float2bfloat16(v[c]);
        __nv_bfloat16 l = __float2bfloat16(v[c] - __bfloat162float(h));
        sh[c] = __bfloat16_as_ushort(h);  sl[c] = __bfloat16_as_ushort(l);
    }
    unsigned long long wh[3], wl[3];
    pack3(sh, wh);  pack3(sl, wl);
    size_t off = (size_t)o * KB + (size_t)i * NFEAT;
    unsigned long long* dh = (unsigned long long*)(g_Bh + off);
    unsigned long long* dl = (unsigned long long*)(g_Bl + off);
#pragma unroll
    for (int j = 0; j < 3; ++j) { dh[j] = wh[j];  dl[j] = wl[j]; }
}

// ---------------- fused GEMM -----------------------------------------------
// CTA 128x256, 8 warps 2(M) x 4(N), warp tile 64x64.
// Prologue: CTA computes+stores its own A_hi/A_lo slice (128 rows x 6144).
// Main: 96 dual iters (A_hi x {B_hi, B_lo}) + 96 single iters (A_lo x B_hi).
__global__ __launch_bounds__(256, 1) void kan_gemm(const float* __restrict__ x,
                                                   float* __restrict__ out) {
    extern __shared__ __align__(1024) unsigned char smem[];
    const uint32_t sbase = smem_u32(smem);
    const int tid  = threadIdx.x;
    const int lane = tid & 31;
    const int wid  = tid >> 5;
    const int warpM = wid & 1;
    const int warpN = wid >> 1;
    const int mBase = blockIdx.y * M_TILE;
    const int nBase = blockIdx.x * N_TILE;

    // ---- prologue: build this CTA's split-A slice in global scratch -------
    {
        const float* xrow = x + (size_t)mBase * IN_F;
#pragma unroll 1
        for (int j = 0; j < (M_TILE * IN_F) / 256; ++j) {   // 256 iters
            int idx = j * 256 + tid;
            int m = idx >> 9, i = idx & 511;
            float bb[NFEAT];
            aug_features(xrow[idx], bb);
            unsigned short sh[NFEAT], sl[NFEAT];
#pragma unroll
            for (int c = 0; c < NFEAT; ++c) {
                __nv_bfloat16 h = __float2bfloat16(bb[c]);
                __nv_bfloat16 l = __float2bfloat16(bb[c] - __bfloat162float(h));
                sh[c] = __bfloat16_as_ushort(h);  sl[c] = __bfloat16_as_ushort(l);
            }
            unsigned long long wh[3], wl[3];
            pack3(sh, wh);  pack3(sl, wl);
            size_t off = (size_t)(mBase + m) * KB + (size_t)i * NFEAT;
            unsigned long long* dh = (unsigned long long*)(g_Ah + off);
            unsigned long long* dl = (unsigned long long*)(g_Al + off);
#pragma unroll
            for (int q = 0; q < 3; ++q) { dh[q] = wh[q];  dl[q] = wl[q]; }
        }
        __threadfence();          // make writes L2-visible before cp.async.cg reads
        __syncthreads();
    }

    const char* Ah = (const char*)(g_Ah + (size_t)mBase * KB);
    const char* Al = (const char*)(g_Al + (size_t)mBase * KB);
    const char* Bh = (const char*)(g_Bh + (size_t)nBase * KB);
    const char* Bl = (const char*)(g_Bl + (size_t)nBase * KB);

    // ---- cp.async coords ---------------------------------------------------
    const int gr = tid >> 3, gc = tid & 7;
    uint32_t aDst[4], bDst[8];
#pragma unroll
    for (int j = 0; j < 4; ++j) aDst[j] = swz(gr + 32 * j, gc);
#pragma unroll
    for (int j = 0; j < 8; ++j) bDst[j] = swz(gr + 32 * j, gc);
    const uint32_t gOff = (uint32_t)gc * 16;

    auto load_stage = [&](int u) {
        const uint32_t st = sbase + (uint32_t)(u & 1) * STAGE_BYTES;
        const bool dual = (u < NCHB);
        const size_t ch = (size_t)(dual ? u : u - NCHB) * 128;
        const char* aB = (dual ? Ah : Al) + ch;
        const char* b1 = Bh + ch;
#pragma unroll
        for (int j = 0; j < 4; ++j)
            cp16(st + aDst[j], aB + (size_t)(gr + 32 * j) * ROWB + gOff);
#pragma unroll
        for (int j = 0; j < 8; ++j)
            cp16(st + A_BYTES + bDst[j], b1 + (size_t)(gr + 32 * j) * ROWB + gOff);
        if (dual) {
            const char* b2 = Bl + ch;
#pragma unroll
            for (int j = 0; j < 8; ++j)
                cp16(st + A_BYTES + B_BYTES + bDst[j],
                     b2 + (size_t)(gr + 32 * j) * ROWB + gOff);
        }
    };

    // ---- ldmatrix lane addressing -----------------------------------------
    const int lr = lane & 15;
    const int lc = lane >> 4;
    uint32_t aOff[4], bOff[4];
#pragma unroll
    for (int t = 0; t < 4; ++t) {
        aOff[t] = swz(warpM * 64 + t * 16 + lr, lc);
        bOff[t] = swz(warpN * 64 + t * 16 + lr, lc);
    }

    float acc[4][8][4];
#pragma unroll
    for (int mt = 0; mt < 4; ++mt)
#pragma unroll
        for (int nt = 0; nt < 8; ++nt)
#pragma unroll
            for (int q = 0; q < 4; ++q) acc[mt][nt][q] = 0.0f;

    load_stage(0);  CP_COMMIT();

#pragma unroll 1
    for (int u = 0; u < NU; ++u) {
        __syncthreads();                 // all warps done with the stage being refilled
        if (u + 1 < NU) { load_stage(u + 1); CP_COMMIT(); CP_WAIT_1(); }
        else           { CP_WAIT_0(); }
        __syncthreads();                 // stage u visible to all warps

        const uint32_t st = sbase + (uint32_t)(u & 1) * STAGE_BYTES;
        const bool dual = (u < NCHB);
#pragma unroll
        for (int s = 0; s < 4; ++s) {
            const uint32_t kx = (uint32_t)s << 5;
            uint32_t a[4][4], b1[4][4];
#pragma unroll
            for (int t = 0; t < 4; ++t)
                ldsm4(a[t][0], a[t][1], a[t][2], a[t][3], st + (aOff[t] ^ kx));
#pragma unroll
            for (int t = 0; t < 4; ++t)
                ldsm4(b1[t][0], b1[t][1], b1[t][2], b1[t][3],
                      st + A_BYTES + (bOff[t] ^ kx));
#pragma unroll
            for (int mt = 0; mt < 4; ++mt)
#pragma unroll
                for (int t = 0; t < 4; ++t) {
                    mma16816(acc[mt][2*t][0], acc[mt][2*t][1], acc[mt][2*t][2], acc[mt][2*t][3],
                             a[mt][0], a[mt][1], a[mt][2], a[mt][3], b1[t][0], b1[t][2]);
                    mma16816(acc[mt][2*t+1][0], acc[mt][2*t+1][1], acc[mt][2*t+1][2], acc[mt][2*t+1][3],
                             a[mt][0], a[mt][1], a[mt][2], a[mt][3], b1[t][1], b1[t][3]);
                }
            if (dual) {
                uint32_t b2[4][4];
#pragma unroll
                for (int t = 0; t < 4; ++t)
                    ldsm4(b2[t][0], b2[t][1], b2[t][2], b2[t][3],
                          st + A_BYTES + B_BYTES + (bOff[t] ^ kx));
#pragma unroll
                for (int mt = 0; mt < 4; ++mt)
#pragma unroll
                    for (int t = 0; t < 4; ++t) {
                        mma16816(acc[mt][2*t][0], acc[mt][2*t][1], acc[mt][2*t][2], acc[mt][2*t][3],
                                 a[mt][0], a[mt][1], a[mt][2], a[mt][3], b2[t][0], b2[t][2]);
                        mma16816(acc[mt][2*t+1][0], acc[mt][2*t+1][1], acc[mt][2*t+1][2], acc[mt][2*t+1][3],
                                 a[mt][0], a[mt][1], a[mt][2], a[mt][3], b2[t][1], b2[t][3]);
                    }
            }
        }
    }

    // ---- epilogue: direct STG of register accumulators --------------------
    const int mRow = mBase + warpM * 64 + (lane >> 2);
    const int nCol = nBase + warpN * 64 + (lane & 3) * 2;
#pragma unroll
    for (int mt = 0; mt < 4; ++mt) {
        float* r0 = out + (size_t)(mRow + mt * 16)     * OUT_F + nCol;
        float* r1 = out + (size_t)(mRow + mt * 16 + 8) * OUT_F + nCol;
#pragma unroll
        for (int nt = 0; nt < 8; ++nt) {
            *(float2*)(r0 + nt * 8) = make_float2(acc[mt][nt][0], acc[mt][nt][1]);
            *(float2*)(r1 + nt * 8) = make_float2(acc[mt][nt][2], acc[mt][nt][3]);
        }
    }
}

// ---------------- launch ---------------------------------------------------
extern "C" void kernel_launch(void* const* d_in, const int* in_sizes, int n_in,
                              void* d_out, int out_size) {
    const float* x  = (const float*)d_in[0];
    const float* bw = (const float*)d_in[1];
    const float* sw = (const float*)d_in[2];
    float* out = (float*)d_out;

    cudaFuncSetAttribute(kan_gemm, cudaFuncAttributeMaxDynamicSharedMemorySize,
                         SMEM_TOTAL);

    prep_B<<<(OUT_F * IN_F) / 256, 256>>>(bw, sw);
    kan_gemm<<<dim3(OUT_F / N_TILE, NBAT / M_TILE), 256, SMEM_TOTAL>>>(x, out);
}